// round 6
// baseline (speedup 1.0000x reference)
#include <cuda_runtime.h>
#include <cstdint>
#include <cstddef>

// ---------------------------------------------------------------------------
// GIN (3-layer) — Round 6.
// Gather: warp-per-(node, 128-float half) — low regs, full occupancy.
// CSR: memset + fused(count&rank + transpose) + scan + atomic-free fill.
// GEMM: mma.sync tf32, BM=64/BN=128.
// ---------------------------------------------------------------------------

#define N_NODES 10000
#define N_EDGES 640000
#define INC     128
#define HIDC    256

__device__ float g_agg[N_NODES * HIDC];
__device__ float g_hid[N_NODES * HIDC];
__device__ float g_f1 [N_NODES * HIDC];
__device__ float g_f2 [N_NODES * HIDC];
__device__ float g_wt [6 * HIDC * HIDC];
__device__ int   g_deg[N_NODES];
__device__ int   g_off[N_NODES + 1];
__device__ int   g_rank[N_EDGES];
__device__ int   g_eid[N_EDGES];

// ---------------------------------------------------------------------------
__device__ __forceinline__ uint32_t smem_u32(const void* p) {
    uint32_t a;
    asm("{ .reg .u64 t; cvta.to.shared.u64 t, %1; cvt.u32.u64 %0, t; }" : "=r"(a) : "l"(p));
    return a;
}
__device__ __forceinline__ float tf32r(float v) {
    uint32_t r;
    asm("cvt.rna.tf32.f32 %0, %1;" : "=r"(r) : "f"(v));
    return __uint_as_float(r);
}
__device__ __forceinline__ void cp16(uint32_t saddr, const void* g, int sz) {
    asm volatile("cp.async.cg.shared.global [%0], [%1], 16, %2;"
                 :: "r"(saddr), "l"(g), "r"(sz) : "memory");
}
__device__ __forceinline__ void cp_commit() {
    asm volatile("cp.async.commit_group;" ::: "memory");
}
template <int N>
__device__ __forceinline__ void cp_wait() {
    asm volatile("cp.async.wait_group %0;" :: "n"(N) : "memory");
}
__device__ __forceinline__ void mma_tf32(float* c, uint32_t a0, uint32_t a1,
                                         uint32_t a2, uint32_t a3,
                                         uint32_t b0, uint32_t b1) {
    asm volatile(
        "mma.sync.aligned.m16n8k8.row.col.f32.tf32.tf32.f32 "
        "{%0,%1,%2,%3}, {%4,%5,%6,%7}, {%8,%9}, {%0,%1,%2,%3};"
        : "+f"(c[0]), "+f"(c[1]), "+f"(c[2]), "+f"(c[3])
        : "r"(a0), "r"(a1), "r"(a2), "r"(a3), "r"(b0), "r"(b1));
}

// ---------------------------------------------------------------------------
// Fused: blocks [0, CNT_BLKS) do degree count + per-edge rank;
// remaining blocks do weight transpose + tf32 rounding.
// ---------------------------------------------------------------------------
#define CNT_BLKS 625
#define TW_ELEMS (256 * INC + 5 * 256 * HIDC)
#define TW_BLKS  ((TW_ELEMS + 255) / 256)

__global__ void __launch_bounds__(256) count_and_transpose(
    const int* __restrict__ ei,
    const float* __restrict__ W0, const float* __restrict__ W1,
    const float* __restrict__ W2, const float* __restrict__ W3,
    const float* __restrict__ W4, const float* __restrict__ W5,
    float* __restrict__ wt)
{
    int b = blockIdx.x;
    if (b < CNT_BLKS) {
        int base = (b * 256 + threadIdx.x) * 4;
        if (base >= N_EDGES) return;
        int4 d = *reinterpret_cast<const int4*>(ei + N_EDGES + base);
        int r0 = atomicAdd(&g_deg[d.x], 1);
        int r1 = atomicAdd(&g_deg[d.y], 1);
        int r2 = atomicAdd(&g_deg[d.z], 1);
        int r3 = atomicAdd(&g_deg[d.w], 1);
        *reinterpret_cast<int4*>(g_rank + base) = make_int4(r0, r1, r2, r3);
    } else {
        int idx = (b - CNT_BLKS) * 256 + threadIdx.x;
        const int S0 = 256 * INC;
        const int S = 256 * HIDC;
        const float* W; int K; int loc; float* out;
        if (idx < S0) { W = W0; K = INC; loc = idx; out = wt; }
        else {
            int r = idx - S0;
            int slot = r / S; loc = r - slot * S; K = HIDC;
            if (slot >= 5) return;
            const float* Ws[5] = { W1, W2, W3, W4, W5 };
            W = Ws[slot]; out = wt + (slot + 1) * HIDC * HIDC;
        }
        int n = loc / K, k = loc - n * K;
        out[(size_t)n * K + k] = tf32r(__ldg(W + (size_t)k * 256 + n));
    }
}

__global__ void __launch_bounds__(1024) scan_kernel() {
    __shared__ int part[1024];
    const int t = threadIdx.x;
    const int CH = 10;
    int local[CH];
    int base = t * CH, s = 0;
    #pragma unroll
    for (int k = 0; k < CH; k++) {
        int idx = base + k;
        local[k] = (idx < N_NODES) ? g_deg[idx] : 0;
        s += local[k];
    }
    part[t] = s;
    __syncthreads();
    for (int d = 1; d < 1024; d <<= 1) {
        int v = (t >= d) ? part[t - d] : 0;
        __syncthreads();
        part[t] += v;
        __syncthreads();
    }
    int run = (t > 0) ? part[t - 1] : 0;
    #pragma unroll
    for (int k = 0; k < CH; k++) {
        int idx = base + k;
        if (idx < N_NODES) { g_off[idx] = run; run += local[k]; }
    }
    if (t == 1023) g_off[N_NODES] = part[1023];
}

__global__ void __launch_bounds__(256) fill_kernel(const int* __restrict__ ei) {
    int base = (blockIdx.x * blockDim.x + threadIdx.x) * 4;
    if (base >= N_EDGES) return;
    int4 s = *reinterpret_cast<const int4*>(ei + base);
    int4 d = *reinterpret_cast<const int4*>(ei + N_EDGES + base);
    int4 r = *reinterpret_cast<const int4*>(g_rank + base);
    g_eid[__ldg(g_off + d.x) + r.x] = s.x;
    g_eid[__ldg(g_off + d.y) + r.y] = s.y;
    g_eid[__ldg(g_off + d.z) + r.z] = s.z;
    g_eid[__ldg(g_off + d.w) + r.w] = s.w;
}

// ---------------------------------------------------------------------------
// gather: one warp per (node, 128-float half). HALVES = C/128.
// agg[n, half] = feat[n, half] + sum_{j in nbrs(n)} feat[j, half]
// Low register footprint -> 8 CTAs/SM (full occupancy).
// ---------------------------------------------------------------------------
template <int HALVES>
__global__ void __launch_bounds__(256, 8) gather_kernel(
    const float* __restrict__ feat, float* __restrict__ agg)
{
    int w = (blockIdx.x * blockDim.x + threadIdx.x) >> 5;
    if (w >= N_NODES * HALVES) return;
    const int node = (HALVES == 2) ? (w >> 1) : w;
    const int half = (HALVES == 2) ? (w & 1) : 0;
    const int lane = threadIdx.x & 31;
    const int C4 = HALVES * 32;
    const int col = half * 32 + lane;

    int beg = __ldg(g_off + node), end = __ldg(g_off + node + 1);
    const float4* f = reinterpret_cast<const float4*>(feat) + col;

    float4 a = __ldg(f + (size_t)node * C4);
    int j = beg;
    for (; j + 3 < end; j += 4) {
        int s0 = __ldg(g_eid + j),     s1 = __ldg(g_eid + j + 1);
        int s2 = __ldg(g_eid + j + 2), s3 = __ldg(g_eid + j + 3);
        float4 v0 = __ldg(f + (size_t)s0 * C4);
        float4 v1 = __ldg(f + (size_t)s1 * C4);
        float4 v2 = __ldg(f + (size_t)s2 * C4);
        float4 v3 = __ldg(f + (size_t)s3 * C4);
        a.x += (v0.x + v1.x) + (v2.x + v3.x);
        a.y += (v0.y + v1.y) + (v2.y + v3.y);
        a.z += (v0.z + v1.z) + (v2.z + v3.z);
        a.w += (v0.w + v1.w) + (v2.w + v3.w);
    }
    for (; j < end; j++) {
        int s0 = __ldg(g_eid + j);
        float4 v0 = __ldg(f + (size_t)s0 * C4);
        a.x += v0.x; a.y += v0.y; a.z += v0.z; a.w += v0.w;
    }
    reinterpret_cast<float4*>(agg)[(size_t)node * C4 + col] = a;
}

// ---------------------------------------------------------------------------
// GEMM: C[M,256] = A[M,K] @ Wt^T (+bias, opt ReLU). mma.sync tf32.
// CTA tile 64x128xK16, 8 warps (2M x 4N), warp tile 32x32.
// ---------------------------------------------------------------------------
#define BM 64
#define BN 128
#define LDT 20
#define ATB (BM * LDT * 4)
#define BTB (BN * LDT * 4)

__global__ void __launch_bounds__(256) gemm_mma(
    const float* __restrict__ A, const float* __restrict__ Bt,
    const float* __restrict__ bias, float* __restrict__ C,
    int M, int K, int relu)
{
    __shared__ __align__(16) float sm[2 * (BM + BN) * LDT];
    float* As[2] = { sm,                 sm + BM * LDT };
    float* Bs[2] = { sm + 2 * BM * LDT,  sm + 2 * BM * LDT + BN * LDT };
    const uint32_t sa_base = smem_u32(sm);
    const uint32_t sb_base = sa_base + 2 * ATB;

    const int tid = threadIdx.x;
    const int lane = tid & 31, wid = tid >> 5;
    const int warp_m = wid & 1, warp_n = wid >> 1;
    const int g = lane >> 2, tig = lane & 3;
    const int nb = blockIdx.x * BN;
    const int mb = blockIdx.y * BM;

    const int lr  = tid >> 2;
    const int lc4 = tid & 3;

    float acc[2][4][4];
    #pragma unroll
    for (int mt = 0; mt < 2; mt++)
        #pragma unroll
        for (int nt = 0; nt < 4; nt++)
            #pragma unroll
            for (int q = 0; q < 4; q++) acc[mt][nt][q] = 0.f;

    const int NC = K >> 4;

    auto issue = [&](int buf, int k0) {
        {
            int grow = mb + lr;
            int rowc = grow < M ? grow : M - 1;
            const float* gp = A + (size_t)rowc * K + k0 + lc4 * 4;
            uint32_t sa = sa_base + buf * ATB + (lr * LDT + lc4 * 4) * 4;
            cp16(sa, gp, grow < M ? 16 : 0);
        }
        #pragma unroll
        for (int t = 0; t < 2; t++) {
            int r = lr + t * 64;
            const float* gp = Bt + (size_t)(nb + r) * K + k0 + lc4 * 4;
            uint32_t sa = sb_base + buf * BTB + (r * LDT + lc4 * 4) * 4;
            cp16(sa, gp, 16);
        }
        cp_commit();
    };

    issue(0, 0);

    for (int i = 0; i < NC; i++) {
        if (i + 1 < NC) issue((i + 1) & 1, (i + 1) << 4);
        if (i + 1 < NC) cp_wait<1>(); else cp_wait<0>();
        __syncthreads();

        const float* as = As[i & 1];
        const float* bs = Bs[i & 1];

        #pragma unroll
        for (int k8 = 0; k8 < 2; k8++) {
            const int kb = k8 * 8;
            uint32_t af[2][4];
            #pragma unroll
            for (int mt = 0; mt < 2; mt++) {
                int rb = warp_m * 32 + mt * 16;
                af[mt][0] = __float_as_uint(tf32r(as[(rb + g)     * LDT + kb + tig]));
                af[mt][1] = __float_as_uint(tf32r(as[(rb + 8 + g) * LDT + kb + tig]));
                af[mt][2] = __float_as_uint(tf32r(as[(rb + g)     * LDT + kb + tig + 4]));
                af[mt][3] = __float_as_uint(tf32r(as[(rb + 8 + g) * LDT + kb + tig + 4]));
            }
            #pragma unroll
            for (int nt = 0; nt < 4; nt++) {
                int cb = warp_n * 32 + nt * 8;
                uint32_t b0 = __float_as_uint(bs[(cb + g) * LDT + kb + tig]);
                uint32_t b1 = __float_as_uint(bs[(cb + g) * LDT + kb + tig + 4]);
                #pragma unroll
                for (int mt = 0; mt < 2; mt++)
                    mma_tf32(acc[mt][nt], af[mt][0], af[mt][1], af[mt][2], af[mt][3], b0, b1);
            }
        }
        __syncthreads();
    }

    #pragma unroll
    for (int nt = 0; nt < 4; nt++) {
        int col = nb + warp_n * 32 + nt * 8 + 2 * tig;
        float2 bv = __ldg(reinterpret_cast<const float2*>(bias + col));
        #pragma unroll
        for (int mt = 0; mt < 2; mt++) {
            int row0 = mb + warp_m * 32 + mt * 16 + g;
            float2 o0 = make_float2(acc[mt][nt][0] + bv.x, acc[mt][nt][1] + bv.y);
            float2 o1 = make_float2(acc[mt][nt][2] + bv.x, acc[mt][nt][3] + bv.y);
            if (relu) {
                o0.x = fmaxf(o0.x, 0.f); o0.y = fmaxf(o0.y, 0.f);
                o1.x = fmaxf(o1.x, 0.f); o1.y = fmaxf(o1.y, 0.f);
            }
            if (row0 < M)
                *reinterpret_cast<float2*>(C + (size_t)row0 * 256 + col) = o0;
            if (row0 + 8 < M)
                *reinterpret_cast<float2*>(C + (size_t)(row0 + 8) * 256 + col) = o1;
        }
    }
}

// ---------------------------------------------------------------------------
static void launch_layer(const float* feat, int C,
                         const float* Wta, const float* ba,
                         const float* Wtb, const float* bb,
                         float* agg, float* hid, float* out, int out_relu)
{
    if (C == INC)
        gather_kernel<1><<<(N_NODES * 32 + 255) / 256, 256>>>(feat, agg);
    else
        gather_kernel<2><<<(N_NODES * 64 + 255) / 256, 256>>>(feat, agg);
    dim3 grid(256 / BN, (N_NODES + BM - 1) / BM);
    gemm_mma<<<grid, 256>>>(agg, Wta, ba, hid, N_NODES, C, 1);
    gemm_mma<<<grid, 256>>>(hid, Wtb, bb, out, N_NODES, HIDC, out_relu);
}

extern "C" void kernel_launch(void* const* d_in, const int* in_sizes, int n_in,
                              void* d_out, int out_size)
{
    const float* x  = (const float*)d_in[0];
    const int*   ei = (const int*)  d_in[1];

    float *agg, *hid, *f1, *f2, *wt;
    int* degp;
    cudaGetSymbolAddress((void**)&agg, g_agg);
    cudaGetSymbolAddress((void**)&hid, g_hid);
    cudaGetSymbolAddress((void**)&f1,  g_f1);
    cudaGetSymbolAddress((void**)&f2,  g_f2);
    cudaGetSymbolAddress((void**)&wt,  g_wt);
    cudaGetSymbolAddress((void**)&degp, g_deg);

    cudaMemsetAsync(degp, 0, N_NODES * sizeof(int));

    count_and_transpose<<<CNT_BLKS + TW_BLKS, 256>>>(
        ei,
        (const float*)d_in[2], (const float*)d_in[4], (const float*)d_in[6],
        (const float*)d_in[8], (const float*)d_in[10], (const float*)d_in[12], wt);
    scan_kernel<<<1, 1024>>>();
    fill_kernel<<<(N_EDGES / 4 + 255) / 256, 256>>>(ei);

    float* Wt[6];
    for (int i = 0; i < 6; i++) Wt[i] = wt + i * HIDC * HIDC;
    const float* bv[6] = { (const float*)d_in[3],  (const float*)d_in[5],
                           (const float*)d_in[7],  (const float*)d_in[9],
                           (const float*)d_in[11], (const float*)d_in[13] };

    launch_layer(x,  INC,  Wt[0], bv[0], Wt[1], bv[1], agg, hid, f1, 1);
    launch_layer(f1, HIDC, Wt[2], bv[2], Wt[3], bv[3], agg, hid, f2, 1);
    launch_layer(f2, HIDC, Wt[4], bv[4], Wt[5], bv[5], agg, hid, (float*)d_out, 0);
}